// round 11
// baseline (speedup 1.0000x reference)
#include <cuda_runtime.h>
#include <cuda_bf16.h>
#include <cstdint>

#define N_NODES 50000
#define N_EDGES 800000
#define IN_DIM 300
#define HID 128
#define NLAYERS 4
#define SCAN_BLOCKS ((N_NODES + 255) / 256)   // 196

// ---------------- device scratch (allocation-free) ----------------
__device__ float g_reps[(NLAYERS + 1) * N_NODES * HID];
__device__ float g_agg[N_NODES * HID];
__device__ float g_tmp[N_NODES * HID];        // h @ lin_r partial
__device__ float g_inv[N_NODES];
__device__ int   g_degi[N_NODES];
__device__ int   g_rowptr[N_NODES + 1];
__device__ int   g_cursor[N_NODES];
__device__ int   g_col[N_EDGES];
__device__ int   g_bsum[SCAN_BLOCKS];
__device__ int   g_boff[SCAN_BLOCKS];
// pre-transposed weight chunks, bf16 hi/lo: 33 chunks x [128 n x 32 words(64 bf16 k)]
__device__ unsigned int g_whi[33 * 4096];
__device__ unsigned int g_wlo[33 * 4096];

// ---------------- helpers ----------------
__device__ __forceinline__ uint32_t smem_to_u32(const void* p) {
    uint32_t a;
    asm("{ .reg .u64 t; cvta.to.shared.u64 t, %1; cvt.u32.u64 %0, t; }" : "=r"(a) : "l"(p));
    return a;
}
__device__ __forceinline__ void ldsm4(uint32_t* r, uint32_t a) {
    asm volatile("ldmatrix.sync.aligned.m8n8.x4.shared.b16 {%0,%1,%2,%3}, [%4];"
                 : "=r"(r[0]), "=r"(r[1]), "=r"(r[2]), "=r"(r[3]) : "r"(a));
}
__device__ __forceinline__ void mma16816(float* c, const uint32_t* a, const uint32_t* b) {
    asm volatile(
        "mma.sync.aligned.m16n8k16.row.col.f32.bf16.bf16.f32 "
        "{%0,%1,%2,%3},{%4,%5,%6,%7},{%8,%9},{%0,%1,%2,%3};"
        : "+f"(c[0]), "+f"(c[1]), "+f"(c[2]), "+f"(c[3])
        : "r"(a[0]), "r"(a[1]), "r"(a[2]), "r"(a[3]), "r"(b[0]), "r"(b[1]));
}
__device__ __forceinline__ void cp_async16(uint32_t dst, const void* src) {
    uint64_t ga;
    asm("cvta.to.global.u64 %0, %1;" : "=l"(ga) : "l"(src));
    asm volatile("cp.async.cg.shared.global [%0], [%1], 16;" :: "r"(dst), "l"(ga) : "memory");
}
__device__ __forceinline__ void cp_commit() { asm volatile("cp.async.commit_group;" ::: "memory"); }
template <int N>
__device__ __forceinline__ void cp_wait() { asm volatile("cp.async.wait_group %0;" :: "n"(N) : "memory"); }

__device__ __forceinline__ unsigned pack_hi(float a, float b, float& ra, float& rb) {
    __nv_bfloat16 ha = __float2bfloat16(a), hb = __float2bfloat16(b);
    ra = a - __bfloat162float(ha);
    rb = b - __bfloat162float(hb);
    return (unsigned)__bfloat16_as_ushort(ha) | ((unsigned)__bfloat16_as_ushort(hb) << 16);
}
__device__ __forceinline__ unsigned pack_lo(float ra, float rb) {
    return (unsigned)__bfloat16_as_ushort(__float2bfloat16(ra)) |
           ((unsigned)__bfloat16_as_ushort(__float2bfloat16(rb)) << 16);
}

// ---------------- CSR build ----------------
__global__ void deg_kernel(const int* __restrict__ ei) {
    int t = blockIdx.x * blockDim.x + threadIdx.x;
    if (t < N_EDGES) atomicAdd(&g_degi[ei[N_EDGES + t]], 1);
}
__global__ void inv_kernel() {
    int t = blockIdx.x * blockDim.x + threadIdx.x;
    if (t < N_NODES) g_inv[t] = 1.0f / (float)max(g_degi[t], 1);
}
__global__ __launch_bounds__(256) void scan1_kernel() {
    __shared__ int sm[256];
    int tid = threadIdx.x;
    int i = blockIdx.x * 256 + tid;
    int v = (i < N_NODES) ? g_degi[i] : 0;
    sm[tid] = v;
    __syncthreads();
#pragma unroll
    for (int off = 1; off < 256; off <<= 1) {
        int t = (tid >= off) ? sm[tid - off] : 0;
        __syncthreads();
        sm[tid] += t;
        __syncthreads();
    }
    if (i < N_NODES) g_rowptr[i] = sm[tid] - v;
    if (tid == 255) g_bsum[blockIdx.x] = sm[255];
}
__global__ __launch_bounds__(256) void scan2_kernel() {
    __shared__ int sm[256];
    int tid = threadIdx.x;
    int v = (tid < SCAN_BLOCKS) ? g_bsum[tid] : 0;
    sm[tid] = v;
    __syncthreads();
#pragma unroll
    for (int off = 1; off < 256; off <<= 1) {
        int t = (tid >= off) ? sm[tid - off] : 0;
        __syncthreads();
        sm[tid] += t;
        __syncthreads();
    }
    if (tid < SCAN_BLOCKS) g_boff[tid] = sm[tid] - v;
}
__global__ __launch_bounds__(256) void scan3_kernel() {
    int tid = threadIdx.x;
    int i = blockIdx.x * 256 + tid;
    if (i < N_NODES) {
        int r = g_rowptr[i] + g_boff[blockIdx.x];
        g_rowptr[i] = r;
        g_cursor[i] = r;
    }
    if (i == 0) g_rowptr[N_NODES] = N_EDGES;
}
__global__ void fill_kernel(const int* __restrict__ ei) {
    int t = blockIdx.x * blockDim.x + threadIdx.x;
    if (t >= N_EDGES) return;
    int dst = ei[N_EDGES + t];
    int pos = atomicAdd(&g_cursor[dst], 1);
    g_col[pos] = ei[t];
}

// ---------------- gather-only mean aggregation (warp per node) ----------------
__global__ __launch_bounds__(256) void agg_kernel(const float* __restrict__ h) {
    int gt = blockIdx.x * blockDim.x + threadIdx.x;
    int node = gt >> 5;
    if (node >= N_NODES) return;
    int lane = gt & 31;
    int beg = g_rowptr[node];
    int end = g_rowptr[node + 1];
    float ax = 0.f, ay = 0.f, az = 0.f, aw = 0.f;
    int e = beg;
    for (; e + 8 <= end; e += 8) {
        float4 v[8];
#pragma unroll
        for (int j = 0; j < 8; j++) {
            int s = __ldg(&g_col[e + j]);
            v[j] = *(const float4*)(h + (size_t)s * HID + lane * 4);
        }
#pragma unroll
        for (int j = 0; j < 8; j++) {
            ax += v[j].x; ay += v[j].y; az += v[j].z; aw += v[j].w;
        }
    }
    for (; e < end; e++) {
        int s = __ldg(&g_col[e]);
        float4 v = *(const float4*)(h + (size_t)s * HID + lane * 4);
        ax += v.x; ay += v.y; az += v.z; aw += v.w;
    }
    float inv = g_inv[node];
    float4 o = make_float4(ax * inv, ay * inv, az * inv, aw * inv);
    *(float4*)(g_agg + (size_t)node * HID + lane * 4) = o;
}

// ---------------- weight prep: transpose + bf16 hi/lo split ----------------
__global__ void prep_w(const float* __restrict__ embW, const float* __restrict__ llW,
                       const float* __restrict__ lrW, const float* __restrict__ f1W,
                       const float* __restrict__ f2W) {
    int t = blockIdx.x * blockDim.x + threadIdx.x;
    if (t >= 33 * 4096) return;
    int chunk = t >> 12, w = t & 4095, n = w >> 5, kp = w & 31, k = kp * 2;
    float v0 = 0.f, v1 = 0.f;
    if (chunk < 5) {
        int kg = chunk * 64 + k;
        if (kg < IN_DIM)     v0 = embW[(size_t)kg * HID + n];
        if (kg + 1 < IN_DIM) v1 = embW[(size_t)(kg + 1) * HID + n];
    } else if (chunk < 21) {
        int L = (chunk - 5) >> 2, c = (chunk - 5) & 3;
        int kg = c * 64 + k;
        const float* W = (kg < 128) ? (llW + (size_t)L * HID * HID + (size_t)kg * HID)
                                    : (lrW + (size_t)L * HID * HID + (size_t)(kg - 128) * HID);
        v0 = W[n]; v1 = W[HID + n];
    } else if (chunk < 31) {
        int kg = (chunk - 21) * 64 + k;
        v0 = f1W[(size_t)kg * HID + n]; v1 = f1W[(size_t)(kg + 1) * HID + n];
    } else {
        int kg = (chunk - 31) * 64 + k;
        v0 = f2W[(size_t)kg * HID + n]; v1 = f2W[(size_t)(kg + 1) * HID + n];
    }
    float r0, r1;
    unsigned hp = pack_hi(v0, v1, r0, r1);
    unsigned lp = pack_lo(r0, r1);
    g_whi[chunk * 4096 + n * 32 + kp] = hp;
    g_wlo[chunk * 4096 + n * 32 + kp] = lp;
}

// ---------------- mma.sync GEMM family (cp.async B double-buffer) ----------------
#define OFF_BIAS 0
#define OFF_G    512
#define OFF_B    1024
#define OFF_AH   2048
#define OFF_AL   (OFF_AH + 18432)      // 20480
#define OFF_BB0  38912
#define OFF_BB1  75776
#define BL_OFF   18432                 // BL within a B buffer
#define SMEM_TOTAL 112640
#define OFF_BOUNCE OFF_AH
#define BSTRIDE 132

__device__ __forceinline__ void issueB(uint32_t sb, uint32_t bufoff, int chunk, int tid) {
#pragma unroll
    for (int it = 0; it < 8; ++it) {
        int idx = tid + it * 256;          // 0..2047
        int half = idx >> 10, w = idx & 1023;
        int row = w >> 3, j = w & 7;
        uint32_t dst = sb + bufoff + half * BL_OFF + row * 144 + j * 16;
        const unsigned* src = (half ? g_wlo : g_whi) + (size_t)chunk * 4096 + w * 4;
        cp_async16(dst, src);
    }
}

// MODE 0: relu(x @ embW + b)                        K=300 (5 chunks)
// MODE 2: relu(concat @ fusW1 + b)                  K=640 (10 chunks)
// MODE 3: A @ fusW2 + b                             K=128 (2 chunks)
// MODE 4: A @ W -> fp32 raw (GEMM_R)                K=128 (2 chunks)
// MODE 5: relu(LN(A@Wl + b + partial(A2)) [+skip])  K=128 (2 chunks)
template <int MODE>
__global__ __launch_bounds__(256)
void gemm_mma(const float* __restrict__ A, const float* __restrict__ A2, int wc0,
              const float* __restrict__ bias, const float* __restrict__ lng,
              const float* __restrict__ lnb, const float* __restrict__ skip,
              float* __restrict__ out)
{
    extern __shared__ char smem[];
    uint32_t sb = smem_to_u32(smem);
    int tid = threadIdx.x, wid = tid >> 5, lane = tid & 31;
    int warp_m = wid & 3, warp_n = wid >> 2;
    int row0 = blockIdx.x * 128;
    const int nch = (MODE == 0) ? 5 : (MODE == 2) ? 10 : 2;

    if (MODE != 4 && tid < HID) {
        *(float*)(smem + OFF_BIAS + tid * 4) = bias[tid];
        if (MODE == 5) {
            *(float*)(smem + OFF_G + tid * 4) = lng[tid];
            *(float*)(smem + OFF_B + tid * 4) = lnb[tid];
        }
    }

    float acc[2][8][4];
#pragma unroll
    for (int mt = 0; mt < 2; mt++)
#pragma unroll
        for (int nt = 0; nt < 8; nt++)
#pragma unroll
            for (int q = 0; q < 4; q++) acc[mt][nt][q] = 0.f;

    uint32_t aOff = sb + (uint32_t)((warp_m * 32 + (lane & 15)) * 144 + (lane >> 4) * 16);
    uint32_t bOff4 = sb + (uint32_t)((warp_n * 64 + ((lane >> 4) & 1) * 8 + (lane & 7)) * 144 +
                                     ((lane >> 3) & 1) * 16);

    issueB(sb, OFF_BB0, wc0, tid);
    cp_commit();

    for (int c = 0; c < nch; ++c) {
        __syncthreads();
        // ---- fill A_hi / A_lo (128 rows x 64 k bf16, 144B stride) ----
#pragma unroll
        for (int it = 0; it < 8; ++it) {
            int idx = tid + it * 256;
            int row = idx >> 4, q = idx & 15, k = q * 4;
            int kg = c * 64 + k, grow = row0 + row;
            float4 v = make_float4(0.f, 0.f, 0.f, 0.f);
            if (grow < N_NODES) {
                if (MODE == 0) {
                    if (kg < IN_DIM) v = *(const float4*)(A + (size_t)grow * IN_DIM + kg);
                } else if (MODE == 2) {
                    int rep = kg >> 7;
                    v = *(const float4*)(A + (size_t)rep * ((size_t)N_NODES * HID) +
                                         (size_t)grow * HID + (kg & 127));
                } else {
                    v = *(const float4*)(A + (size_t)grow * HID + kg);
                }
            }
            float r0, r1, r2, r3;
            unsigned h01 = pack_hi(v.x, v.y, r0, r1);
            unsigned h23 = pack_hi(v.z, v.w, r2, r3);
            unsigned l01 = pack_lo(r0, r1);
            unsigned l23 = pack_lo(r2, r3);
            int off = row * 144 + k * 2;
            *(uint2*)(smem + OFF_AH + off) = make_uint2(h01, h23);
            *(uint2*)(smem + OFF_AL + off) = make_uint2(l01, l23);
        }
        if (c + 1 < nch) {
            issueB(sb, ((c + 1) & 1) ? OFF_BB1 : OFF_BB0, wc0 + c + 1, tid);
            cp_commit();
            cp_wait<1>();
        } else {
            cp_wait<0>();
        }
        __syncthreads();
        uint32_t bbase = (c & 1) ? OFF_BB1 : OFF_BB0;
#pragma unroll
        for (int ks = 0; ks < 4; ++ks) {
            uint32_t ah[2][4], al[2][4];
#pragma unroll
            for (int mt = 0; mt < 2; mt++) {
                ldsm4(ah[mt], aOff + OFF_AH + mt * 16 * 144 + ks * 32);
                ldsm4(al[mt], aOff + OFF_AL + mt * 16 * 144 + ks * 32);
            }
#pragma unroll
            for (int nt2 = 0; nt2 < 4; ++nt2) {
                uint32_t bh[4], bl[4];
                ldsm4(bh, bOff4 + bbase + nt2 * 16 * 144 + ks * 32);
                ldsm4(bl, bOff4 + bbase + BL_OFF + nt2 * 16 * 144 + ks * 32);
#pragma unroll
                for (int mt = 0; mt < 2; mt++) {
                    mma16816(acc[mt][2 * nt2],     ah[mt], &bh[0]);
                    mma16816(acc[mt][2 * nt2 + 1], ah[mt], &bh[2]);
                    mma16816(acc[mt][2 * nt2],     ah[mt], &bl[0]);
                    mma16816(acc[mt][2 * nt2 + 1], ah[mt], &bl[2]);
                    mma16816(acc[mt][2 * nt2],     al[mt], &bh[0]);
                    mma16816(acc[mt][2 * nt2 + 1], al[mt], &bh[2]);
                }
            }
        }
    }

    int tq = lane >> 2, tr = lane & 3;

    if (MODE == 4) {
        // slim epilogue: raw fp32 direct stores (no bounce, no barrier)
#pragma unroll
        for (int mt = 0; mt < 2; mt++) {
#pragma unroll
            for (int nt = 0; nt < 8; nt++) {
                int col = warp_n * 64 + nt * 8 + tr * 2;
                int g0 = row0 + warp_m * 32 + mt * 16 + tq;
                if (g0 < N_NODES)
                    *(float2*)(out + (size_t)g0 * HID + col) =
                        make_float2(acc[mt][nt][0], acc[mt][nt][1]);
                if (g0 + 8 < N_NODES)
                    *(float2*)(out + (size_t)(g0 + 8) * HID + col) =
                        make_float2(acc[mt][nt][2], acc[mt][nt][3]);
            }
        }
        return;
    }

    __syncthreads();
    // ---- dump accs (+bias, +partial for MODE 5, +relu for MODE 0/2) to bounce ----
    {
        float* bounce = (float*)(smem + OFF_BOUNCE);
        const float* sbias = (const float*)(smem + OFF_BIAS);
#pragma unroll
        for (int mt = 0; mt < 2; mt++) {
#pragma unroll
            for (int nt = 0; nt < 8; nt++) {
                int col = warp_n * 64 + nt * 8 + tr * 2;
                float b0 = sbias[col], b1 = sbias[col + 1];
                int r0 = warp_m * 32 + mt * 16 + tq;
                float x0 = acc[mt][nt][0] + b0, x1 = acc[mt][nt][1] + b1;
                float x2 = acc[mt][nt][2] + b0, x3 = acc[mt][nt][3] + b1;
                if (MODE == 5) {
                    int g0 = row0 + r0;
                    if (g0 < N_NODES) {
                        float2 p = *(const float2*)(A2 + (size_t)g0 * HID + col);
                        x0 += p.x; x1 += p.y;
                    }
                    if (g0 + 8 < N_NODES) {
                        float2 p = *(const float2*)(A2 + (size_t)(g0 + 8) * HID + col);
                        x2 += p.x; x3 += p.y;
                    }
                }
                if (MODE == 0 || MODE == 2) {
                    x0 = fmaxf(x0, 0.f); x1 = fmaxf(x1, 0.f);
                    x2 = fmaxf(x2, 0.f); x3 = fmaxf(x3, 0.f);
                }
                *(float2*)(bounce + r0 * BSTRIDE + col)       = make_float2(x0, x1);
                *(float2*)(bounce + (r0 + 8) * BSTRIDE + col) = make_float2(x2, x3);
            }
        }
    }
    __syncthreads();

    // ---- LN pass (MODE 5): thread per row ----
    if (MODE == 5 && tid < 128) {
        float* bounce = (float*)(smem + OFF_BOUNCE);
        const float* sg = (const float*)(smem + OFF_G);
        const float* sbe = (const float*)(smem + OFF_B);
        float s = 0.f, s2 = 0.f;
#pragma unroll
        for (int j = 0; j < HID; j++) {
            float x = bounce[tid * BSTRIDE + j];
            s += x; s2 += x * x;
        }
        float mean = s * (1.0f / HID);
        float var = s2 * (1.0f / HID) - mean * mean;
        float rs = rsqrtf(var + 1e-5f);
#pragma unroll
        for (int j = 0; j < HID; j++) {
            float x = bounce[tid * BSTRIDE + j];
            bounce[tid * BSTRIDE + j] = (x - mean) * rs * sg[j] + sbe[j];
        }
    }
    if (MODE == 5) __syncthreads();

    // ---- coalesced store (+skip+relu for MODE 5) ----
    {
        const float* bounce = (const float*)(smem + OFF_BOUNCE);
#pragma unroll
        for (int it = 0; it < 16; ++it) {
            int idx4 = tid + it * 256;
            int row = idx4 >> 5, c4 = idx4 & 31;
            int grow = row0 + row;
            if (grow < N_NODES) {
                float4 v = *(const float4*)(bounce + row * BSTRIDE + c4 * 4);
                if (MODE == 5) {
                    if (skip) {
                        float4 sk = *(const float4*)(skip + (size_t)grow * HID + c4 * 4);
                        v.x += sk.x; v.y += sk.y; v.z += sk.z; v.w += sk.w;
                    }
                    v.x = fmaxf(v.x, 0.f); v.y = fmaxf(v.y, 0.f);
                    v.z = fmaxf(v.z, 0.f); v.w = fmaxf(v.w, 0.f);
                }
                *(float4*)(out + (size_t)grow * HID + c4 * 4) = v;
            }
        }
    }
}

// ---------------- launch ----------------
extern "C" void kernel_launch(void* const* d_in, const int* in_sizes, int n_in,
                              void* d_out, int out_size)
{
    const float* x       = (const float*)d_in[0];
    const int*   ei      = (const int*)  d_in[1];
    const float* emb_W   = (const float*)d_in[2];
    const float* emb_b   = (const float*)d_in[3];
    const float* lin_l_W = (const float*)d_in[4];
    const float* lin_l_b = (const float*)d_in[5];
    const float* lin_r_W = (const float*)d_in[6];
    const float* ln_g    = (const float*)d_in[7];
    const float* ln_b    = (const float*)d_in[8];
    const float* fus_W1  = (const float*)d_in[9];
    const float* fus_b1  = (const float*)d_in[10];
    const float* fus_W2  = (const float*)d_in[11];
    const float* fus_b2  = (const float*)d_in[12];
    float* out = (float*)d_out;

    float *reps, *agg, *tmp;
    int* degi;
    cudaGetSymbolAddress((void**)&reps, g_reps);
    cudaGetSymbolAddress((void**)&agg,  g_agg);
    cudaGetSymbolAddress((void**)&tmp,  g_tmp);
    cudaGetSymbolAddress((void**)&degi, g_degi);

    cudaFuncSetAttribute(gemm_mma<0>, cudaFuncAttributeMaxDynamicSharedMemorySize, SMEM_TOTAL);
    cudaFuncSetAttribute(gemm_mma<2>, cudaFuncAttributeMaxDynamicSharedMemorySize, SMEM_TOTAL);
    cudaFuncSetAttribute(gemm_mma<3>, cudaFuncAttributeMaxDynamicSharedMemorySize, SMEM_TOTAL);
    cudaFuncSetAttribute(gemm_mma<4>, cudaFuncAttributeMaxDynamicSharedMemorySize, SMEM_TOTAL);
    cudaFuncSetAttribute(gemm_mma<5>, cudaFuncAttributeMaxDynamicSharedMemorySize, SMEM_TOTAL);

    // side stream + events (host-side objects only; created once)
    static cudaStream_t s2 = nullptr;
    static cudaEvent_t evF = nullptr, evH[NLAYERS + 1], evA[NLAYERS];
    if (s2 == nullptr) {
        cudaStreamCreateWithFlags(&s2, cudaStreamNonBlocking);
        cudaEventCreateWithFlags(&evF, cudaEventDisableTiming);
        for (int i = 0; i <= NLAYERS; i++) cudaEventCreateWithFlags(&evH[i], cudaEventDisableTiming);
        for (int i = 0; i < NLAYERS; i++) cudaEventCreateWithFlags(&evA[i], cudaEventDisableTiming);
    }

    // fork: CSR build on s2; weight prep + embed GEMM on main
    cudaEventRecord(evF, 0);
    cudaStreamWaitEvent(s2, evF, 0);
    cudaMemsetAsync(degi, 0, N_NODES * sizeof(int), s2);
    deg_kernel<<<(N_EDGES + 255) / 256, 256, 0, s2>>>(ei);
    inv_kernel<<<(N_NODES + 255) / 256, 256, 0, s2>>>();
    scan1_kernel<<<SCAN_BLOCKS, 256, 0, s2>>>();
    scan2_kernel<<<1, 256, 0, s2>>>();
    scan3_kernel<<<SCAN_BLOCKS, 256, 0, s2>>>();
    fill_kernel<<<(N_EDGES + 255) / 256, 256, 0, s2>>>(ei);

    prep_w<<<(33 * 4096 + 255) / 256, 256>>>(emb_W, lin_l_W, lin_r_W, fus_W1, fus_W2);

    const int GB = (N_NODES + 127) / 128;  // 391

    gemm_mma<0><<<GB, 256, SMEM_TOTAL>>>(x, nullptr, 0, emb_b,
                                         nullptr, nullptr, nullptr, reps);
    cudaEventRecord(evH[0], 0);

    for (int i = 0; i < NLAYERS; i++) {
        float* h  = reps + (size_t)i * N_NODES * HID;
        float* hn = reps + (size_t)(i + 1) * N_NODES * HID;
        // side stream: aggregation (waits for h and, in-order, CSR)
        cudaStreamWaitEvent(s2, evH[i], 0);
        agg_kernel<<<(N_NODES * 32 + 255) / 256, 256, 0, s2>>>(h);
        cudaEventRecord(evA[i], s2);
        // main: h @ lin_r concurrently
        gemm_mma<4><<<GB, 256, SMEM_TOTAL>>>(h, nullptr, 5 + i * 4 + 2, nullptr,
                                             nullptr, nullptr, nullptr, tmp);
        // join, then agg @ lin_l + partial + LN + skip + relu
        cudaStreamWaitEvent(0, evA[i], 0);
        gemm_mma<5><<<GB, 256, SMEM_TOTAL>>>(agg, tmp, 5 + i * 4,
                                             lin_l_b + i * HID,
                                             ln_g + i * HID, ln_b + i * HID,
                                             (i > 0) ? h : nullptr, hn);
        cudaEventRecord(evH[i + 1], 0);
    }
    gemm_mma<2><<<GB, 256, SMEM_TOTAL>>>(reps, nullptr, 21, fus_b1,
                                         nullptr, nullptr, nullptr, agg);
    gemm_mma<3><<<GB, 256, SMEM_TOTAL>>>(agg, nullptr, 31, fus_b2,
                                         nullptr, nullptr, nullptr, out);
}

// round 13
// speedup vs baseline: 1.0008x; 1.0008x over previous
#include <cuda_runtime.h>
#include <cuda_bf16.h>
#include <cstdint>

#define N_NODES 50000
#define N_EDGES 800000
#define IN_DIM 300
#define HID 128
#define NLAYERS 4
#define SCAN_BLOCKS ((N_NODES + 255) / 256)   // 196
#define ROWPAD 128

// ---------------- device scratch (allocation-free) ----------------
// activations stored as packed bf16 hi/lo: row = 64 uint words = 128 cols
__device__ unsigned g_rhi[((NLAYERS + 1) * N_NODES + ROWPAD) * 64];
__device__ unsigned g_rlo[((NLAYERS + 1) * N_NODES + ROWPAD) * 64];
__device__ unsigned g_ahi[(N_NODES + ROWPAD) * 64];
__device__ unsigned g_alo[(N_NODES + ROWPAD) * 64];
__device__ float g_inv[N_NODES];
__device__ int   g_degi[N_NODES];
__device__ int   g_rowptr[N_NODES + 1];
__device__ int   g_cursor[N_NODES];
__device__ int   g_col[N_EDGES];
__device__ int   g_bsum[SCAN_BLOCKS];
__device__ int   g_boff[SCAN_BLOCKS];
// pre-transposed weight chunks, bf16 hi/lo: 33 chunks x [128 n x 32 words]
__device__ unsigned g_whi[33 * 4096];
__device__ unsigned g_wlo[33 * 4096];

// ---------------- helpers ----------------
__device__ __forceinline__ uint32_t smem_to_u32(const void* p) {
    uint32_t a;
    asm("{ .reg .u64 t; cvta.to.shared.u64 t, %1; cvt.u32.u64 %0, t; }" : "=r"(a) : "l"(p));
    return a;
}
__device__ __forceinline__ void ldsm4(uint32_t* r, uint32_t a) {
    asm volatile("ldmatrix.sync.aligned.m8n8.x4.shared.b16 {%0,%1,%2,%3}, [%4];"
                 : "=r"(r[0]), "=r"(r[1]), "=r"(r[2]), "=r"(r[3]) : "r"(a));
}
__device__ __forceinline__ void mma16816(float* c, const uint32_t* a, const uint32_t* b) {
    asm volatile(
        "mma.sync.aligned.m16n8k16.row.col.f32.bf16.bf16.f32 "
        "{%0,%1,%2,%3},{%4,%5,%6,%7},{%8,%9},{%0,%1,%2,%3};"
        : "+f"(c[0]), "+f"(c[1]), "+f"(c[2]), "+f"(c[3])
        : "r"(a[0]), "r"(a[1]), "r"(a[2]), "r"(a[3]), "r"(b[0]), "r"(b[1]));
}
__device__ __forceinline__ void cp_async16(uint32_t dst, const void* src) {
    uint64_t ga;
    asm("cvta.to.global.u64 %0, %1;" : "=l"(ga) : "l"(src));
    asm volatile("cp.async.cg.shared.global [%0], [%1], 16;" :: "r"(dst), "l"(ga) : "memory");
}
__device__ __forceinline__ void cp_commit() { asm volatile("cp.async.commit_group;" ::: "memory"); }
template <int N>
__device__ __forceinline__ void cp_wait() { asm volatile("cp.async.wait_group %0;" :: "n"(N) : "memory"); }

__device__ __forceinline__ unsigned pack_hi(float a, float b, float& ra, float& rb) {
    __nv_bfloat16 ha = __float2bfloat16(a), hb = __float2bfloat16(b);
    ra = a - __bfloat162float(ha);
    rb = b - __bfloat162float(hb);
    return (unsigned)__bfloat16_as_ushort(ha) | ((unsigned)__bfloat16_as_ushort(hb) << 16);
}
__device__ __forceinline__ unsigned pack_lo(float ra, float rb) {
    return (unsigned)__bfloat16_as_ushort(__float2bfloat16(ra)) |
           ((unsigned)__bfloat16_as_ushort(__float2bfloat16(rb)) << 16);
}
// unpack bf16x2 hi/lo word pair -> 2 floats (reconstructed)
__device__ __forceinline__ float up_lo(unsigned h, unsigned l) {
    return __uint_as_float(h << 16) + __uint_as_float(l << 16);
}
__device__ __forceinline__ float up_hi(unsigned h, unsigned l) {
    return __uint_as_float(h & 0xffff0000u) + __uint_as_float(l & 0xffff0000u);
}

// ---------------- CSR build ----------------
__global__ void deg_kernel(const int* __restrict__ ei) {
    int t = blockIdx.x * blockDim.x + threadIdx.x;
    if (t < N_EDGES) atomicAdd(&g_degi[ei[N_EDGES + t]], 1);
}
__global__ void inv_kernel() {
    int t = blockIdx.x * blockDim.x + threadIdx.x;
    if (t < N_NODES) g_inv[t] = 1.0f / (float)max(g_degi[t], 1);
}
__global__ __launch_bounds__(256) void scan1_kernel() {
    __shared__ int sm[256];
    int tid = threadIdx.x;
    int i = blockIdx.x * 256 + tid;
    int v = (i < N_NODES) ? g_degi[i] : 0;
    sm[tid] = v;
    __syncthreads();
#pragma unroll
    for (int off = 1; off < 256; off <<= 1) {
        int t = (tid >= off) ? sm[tid - off] : 0;
        __syncthreads();
        sm[tid] += t;
        __syncthreads();
    }
    if (i < N_NODES) g_rowptr[i] = sm[tid] - v;
    if (tid == 255) g_bsum[blockIdx.x] = sm[255];
}
__global__ __launch_bounds__(256) void scan2_kernel() {
    __shared__ int sm[256];
    int tid = threadIdx.x;
    int v = (tid < SCAN_BLOCKS) ? g_bsum[tid] : 0;
    sm[tid] = v;
    __syncthreads();
#pragma unroll
    for (int off = 1; off < 256; off <<= 1) {
        int t = (tid >= off) ? sm[tid - off] : 0;
        __syncthreads();
        sm[tid] += t;
        __syncthreads();
    }
    if (tid < SCAN_BLOCKS) g_boff[tid] = sm[tid] - v;
}
__global__ __launch_bounds__(256) void scan3_kernel() {
    int tid = threadIdx.x;
    int i = blockIdx.x * 256 + tid;
    if (i < N_NODES) {
        int r = g_rowptr[i] + g_boff[blockIdx.x];
        g_rowptr[i] = r;
        g_cursor[i] = r;
    }
    if (i == 0) g_rowptr[N_NODES] = N_EDGES;
}
__global__ void fill_kernel(const int* __restrict__ ei) {
    int t = blockIdx.x * blockDim.x + threadIdx.x;
    if (t >= N_EDGES) return;
    int dst = ei[N_EDGES + t];
    int pos = atomicAdd(&g_cursor[dst], 1);
    g_col[pos] = ei[t];
}

// ---------------- gather-only mean aggregation (warp per node, packed in/out) ----------------
__global__ __launch_bounds__(256) void agg_kernel(const unsigned* __restrict__ hhi,
                                                  const unsigned* __restrict__ hlo) {
    int gt = blockIdx.x * blockDim.x + threadIdx.x;
    int node = gt >> 5;
    if (node >= N_NODES) return;
    int lane = gt & 31;
    int beg = g_rowptr[node];
    int end = g_rowptr[node + 1];
    float ax = 0.f, ay = 0.f, az = 0.f, aw = 0.f;
    int e = beg;
    for (; e + 4 <= end; e += 4) {
        uint2 hv[4], lv[4];
#pragma unroll
        for (int j = 0; j < 4; j++) {
            int s = __ldg(&g_col[e + j]);
            hv[j] = *(const uint2*)(hhi + (size_t)s * 64 + lane * 2);
            lv[j] = *(const uint2*)(hlo + (size_t)s * 64 + lane * 2);
        }
#pragma unroll
        for (int j = 0; j < 4; j++) {
            ax += up_lo(hv[j].x, lv[j].x);
            ay += up_hi(hv[j].x, lv[j].x);
            az += up_lo(hv[j].y, lv[j].y);
            aw += up_hi(hv[j].y, lv[j].y);
        }
    }
    for (; e < end; e++) {
        int s = __ldg(&g_col[e]);
        uint2 hv = *(const uint2*)(hhi + (size_t)s * 64 + lane * 2);
        uint2 lv = *(const uint2*)(hlo + (size_t)s * 64 + lane * 2);
        ax += up_lo(hv.x, lv.x);
        ay += up_hi(hv.x, lv.x);
        az += up_lo(hv.y, lv.y);
        aw += up_hi(hv.y, lv.y);
    }
    float inv = g_inv[node];
    ax *= inv; ay *= inv; az *= inv; aw *= inv;
    float r0, r1, r2, r3;
    unsigned h01 = pack_hi(ax, ay, r0, r1);
    unsigned h23 = pack_hi(az, aw, r2, r3);
    unsigned l01 = pack_lo(r0, r1);
    unsigned l23 = pack_lo(r2, r3);
    *(uint2*)(g_ahi + (size_t)node * 64 + lane * 2) = make_uint2(h01, h23);
    *(uint2*)(g_alo + (size_t)node * 64 + lane * 2) = make_uint2(l01, l23);
}

// ---------------- weight prep: transpose + bf16 hi/lo split ----------------
__global__ void prep_w(const float* __restrict__ embW, const float* __restrict__ llW,
                       const float* __restrict__ lrW, const float* __restrict__ f1W,
                       const float* __restrict__ f2W) {
    int t = blockIdx.x * blockDim.x + threadIdx.x;
    if (t >= 33 * 4096) return;
    int chunk = t >> 12, w = t & 4095, n = w >> 5, kp = w & 31, k = kp * 2;
    float v0 = 0.f, v1 = 0.f;
    if (chunk < 5) {
        int kg = chunk * 64 + k;
        if (kg < IN_DIM)     v0 = embW[(size_t)kg * HID + n];
        if (kg + 1 < IN_DIM) v1 = embW[(size_t)(kg + 1) * HID + n];
    } else if (chunk < 21) {
        int L = (chunk - 5) >> 2, c = (chunk - 5) & 3;
        int kg = c * 64 + k;
        const float* W = (kg < 128) ? (llW + (size_t)L * HID * HID + (size_t)kg * HID)
                                    : (lrW + (size_t)L * HID * HID + (size_t)(kg - 128) * HID);
        v0 = W[n]; v1 = W[HID + n];
    } else if (chunk < 31) {
        int kg = (chunk - 21) * 64 + k;
        v0 = f1W[(size_t)kg * HID + n]; v1 = f1W[(size_t)(kg + 1) * HID + n];
    } else {
        int kg = (chunk - 31) * 64 + k;
        v0 = f2W[(size_t)kg * HID + n]; v1 = f2W[(size_t)(kg + 1) * HID + n];
    }
    float r0, r1;
    unsigned hp = pack_hi(v0, v1, r0, r1);
    unsigned lp = pack_lo(r0, r1);
    g_whi[chunk * 4096 + n * 32 + kp] = hp;
    g_wlo[chunk * 4096 + n * 32 + kp] = lp;
}

// ---------------- mma.sync GEMM family (cp.async: A double-buffer, B single) ----------------
#define OFF_BIAS 0
#define OFF_G    512
#define OFF_B    1024
#define OFF_A0   2048
#define OFF_A1   38912
#define OFF_BB   75776
#define HALF_OFF 18432        // lo half within an A buffer / B buffer
#define SMEM_TOTAL 112640
#define OFF_BOUNCE OFF_A0     // 67584B fits in A0+A1 (73728)
#define BSTRIDE 132

__device__ __forceinline__ void issueB(uint32_t sb, int chunk, int tid) {
#pragma unroll
    for (int it = 0; it < 8; ++it) {
        int idx = tid + it * 256;
        int half = idx >> 10, w = idx & 1023;
        int row = w >> 3, j = w & 7;
        uint32_t dst = sb + OFF_BB + half * HALF_OFF + row * 144 + j * 16;
        const unsigned* src = (half ? g_wlo : g_whi) + (size_t)chunk * 4096 + w * 4;
        cp_async16(dst, src);
    }
}
__device__ __forceinline__ void issueA(uint32_t sb, uint32_t abuf, const unsigned* hiP,
                                       const unsigned* loP, int row0, int tid) {
#pragma unroll
    for (int it = 0; it < 8; ++it) {
        int idx = tid + it * 256;
        int half = idx >> 10, w = idx & 1023;
        int row = w >> 3, j = w & 7;
        uint32_t dst = sb + abuf + half * HALF_OFF + row * 144 + j * 16;
        const unsigned* src = (half ? loP : hiP) + (size_t)(row0 + row) * 64 + j * 4;
        cp_async16(dst, src);
    }
}

// MODE 0: relu(x @ embW + b) -> packed              K=300 (5 chunks, fp32 A path)
// MODE 1: relu(LN(agg@Wl + b + h@Wr) [+skip]) -> packed  K=256 (4 chunks)
// MODE 2: relu(concat @ fusW1 + b) -> packed        K=640 (10 chunks)
// MODE 3: A @ fusW2 + b -> fp32 out                 K=128 (2 chunks)
template <int MODE>
__global__ __launch_bounds__(256)
void gemm_mma(const float* __restrict__ Af,
              const unsigned* __restrict__ Ahi, const unsigned* __restrict__ Alo,
              const unsigned* __restrict__ A2hi, const unsigned* __restrict__ A2lo,
              int wc0, const float* __restrict__ bias,
              const float* __restrict__ lng, const float* __restrict__ lnb,
              const unsigned* __restrict__ skHi, const unsigned* __restrict__ skLo,
              float* __restrict__ outF,
              unsigned* __restrict__ outHi, unsigned* __restrict__ outLo)
{
    extern __shared__ char smem[];
    uint32_t sb = smem_to_u32(smem);
    int tid = threadIdx.x, wid = tid >> 5, lane = tid & 31;
    int warp_m = wid & 3, warp_n = wid >> 2;
    int row0 = blockIdx.x * 128;
    const int nch = (MODE == 0) ? 5 : (MODE == 2) ? 10 : (MODE == 1) ? 4 : 2;

    if (tid < HID) {
        *(float*)(smem + OFF_BIAS + tid * 4) = bias[tid];
        if (MODE == 1) {
            *(float*)(smem + OFF_G + tid * 4) = lng[tid];
            *(float*)(smem + OFF_B + tid * 4) = lnb[tid];
        }
    }

    float acc[2][8][4];
#pragma unroll
    for (int mt = 0; mt < 2; mt++)
#pragma unroll
        for (int nt = 0; nt < 8; nt++)
#pragma unroll
            for (int q = 0; q < 4; q++) acc[mt][nt][q] = 0.f;

    uint32_t aOff = sb + (uint32_t)((warp_m * 32 + (lane & 15)) * 144 + (lane >> 4) * 16);
    uint32_t bOff4 = sb + (uint32_t)((warp_n * 64 + ((lane >> 4) & 1) * 8 + (lane & 7)) * 144 +
                                     ((lane >> 3) & 1) * 16) + OFF_BB;

    // chunk -> packed A source
    auto srcA = [&](int c, const unsigned*& hp, const unsigned*& lp) {
        if (MODE == 1) {
            if (c < 2) { hp = Ahi + c * 32;        lp = Alo + c * 32; }
            else       { hp = A2hi + (c - 2) * 32; lp = A2lo + (c - 2) * 32; }
        } else if (MODE == 2) {
            size_t rb = (size_t)(c >> 1) * ((size_t)N_NODES * 64) + (size_t)(c & 1) * 32;
            hp = Ahi + rb; lp = Alo + rb;
        } else {  // MODE 3
            hp = Ahi + c * 32; lp = Alo + c * 32;
        }
    };

    if (MODE != 0) {
        const unsigned *hp, *lp;
        srcA(0, hp, lp);
        issueA(sb, OFF_A0, hp, lp, row0, tid);
        cp_commit();
    }

    for (int c = 0; c < nch; ++c) {
        __syncthreads();
        if (MODE == 0) {
            // fp32 register path into A0 (always)
#pragma unroll
            for (int it = 0; it < 8; ++it) {
                int idx = tid + it * 256;
                int row = idx >> 4, q = idx & 15, k = q * 4;
                int kg = c * 64 + k, grow = row0 + row;
                float4 v = make_float4(0.f, 0.f, 0.f, 0.f);
                if (grow < N_NODES && kg < IN_DIM)
                    v = *(const float4*)(Af + (size_t)grow * IN_DIM + kg);
                float r0, r1, r2, r3;
                unsigned h01 = pack_hi(v.x, v.y, r0, r1);
                unsigned h23 = pack_hi(v.z, v.w, r2, r3);
                unsigned l01 = pack_lo(r0, r1);
                unsigned l23 = pack_lo(r2, r3);
                int off = row * 144 + k * 2;
                *(uint2*)(smem + OFF_A0 + off) = make_uint2(h01, h23);
                *(uint2*)(smem + OFF_A0 + HALF_OFF + off) = make_uint2(l01, l23);
            }
            issueB(sb, wc0 + c, tid);
            cp_commit();
            cp_wait<0>();
        } else {
            issueB(sb, wc0 + c, tid);
            cp_commit();
            if (c + 1 < nch) {
                const unsigned *hp, *lp;
                srcA(c + 1, hp, lp);
                issueA(sb, ((c + 1) & 1) ? OFF_A1 : OFF_A0, hp, lp, row0, tid);
                cp_commit();
                cp_wait<1>();
            } else {
                cp_wait<0>();
            }
        }
        __syncthreads();
        uint32_t abase = (MODE == 0) ? OFF_A0 : ((c & 1) ? OFF_A1 : OFF_A0);
#pragma unroll
        for (int ks = 0; ks < 4; ++ks) {
            uint32_t ah[2][4], al[2][4];
#pragma unroll
            for (int mt = 0; mt < 2; mt++) {
                ldsm4(ah[mt], aOff + abase + mt * 16 * 144 + ks * 32);
                ldsm4(al[mt], aOff + abase + HALF_OFF + mt * 16 * 144 + ks * 32);
            }
#pragma unroll
            for (int nt2 = 0; nt2 < 4; ++nt2) {
                uint32_t bh[4], bl[4];
                ldsm4(bh, bOff4 + nt2 * 16 * 144 + ks * 32);
                ldsm4(bl, bOff4 + HALF_OFF + nt2 * 16 * 144 + ks * 32);
#pragma unroll
                for (int mt = 0; mt < 2; mt++) {
                    mma16816(acc[mt][2 * nt2],     ah[mt], &bh[0]);
                    mma16816(acc[mt][2 * nt2 + 1], ah[mt], &bh[2]);
                    mma16816(acc[mt][2 * nt2],     ah[mt], &bl[0]);
                    mma16816(acc[mt][2 * nt2 + 1], ah[mt], &bl[2]);
                    mma16816(acc[mt][2 * nt2],     al[mt], &bh[0]);
                    mma16816(acc[mt][2 * nt2 + 1], al[mt], &bh[2]);
                }
            }
        }
    }
    __syncthreads();

    // ---- dump accs (+bias) to bounce; relu for MODE 0/2 ----
    {
        float* bounce = (float*)(smem + OFF_BOUNCE);
        const float* sbias = (const float*)(smem + OFF_BIAS);
        int tq = lane >> 2, tr = lane & 3;
#pragma unroll
        for (int mt = 0; mt < 2; mt++) {
#pragma unroll
            for (int nt = 0; nt < 8; nt++) {
                int col = warp_n * 64 + nt * 8 + tr * 2;
                float b0 = sbias[col], b1 = sbias[col + 1];
                int r0 = warp_m * 32 + mt * 16 + tq;
                float x0 = acc[mt][nt][0] + b0, x1 = acc[mt][nt][1] + b1;
                float x2 = acc[mt][nt][2] + b0, x3 = acc[mt][nt][3] + b1;
                if (MODE == 0 || MODE == 2) {
                    x0 = fmaxf(x0, 0.f); x1 = fmaxf(x1, 0.f);
                    x2 = fmaxf(x2, 0.f); x3 = fmaxf(x3, 0.f);
                }
                *(float2*)(bounce + r0 * BSTRIDE + col)       = make_float2(x0, x1);
                *(float2*)(bounce + (r0 + 8) * BSTRIDE + col) = make_float2(x2, x3);
            }
        }
    }
    __syncthreads();

    // ---- LN pass (MODE 1): thread per row ----
    if (MODE == 1 && tid < 128) {
        float* bounce = (float*)(smem + OFF_BOUNCE);
        const float* sg = (const float*)(smem + OFF_G);
        const float* sbe = (const float*)(smem + OFF_B);
        float s = 0.f, s2 = 0.f;
#pragma unroll
        for (int j = 0; j < HID; j++) {
            float x = bounce[tid * BSTRIDE + j];
            s += x; s2 += x * x;
        }
        float mean = s * (1.0f / HID);
        float var = s2 * (1.0f / HID) - mean * mean;
        float rs = rsqrtf(var + 1e-5f);
#pragma unroll
        for (int j = 0; j < HID; j++) {
            float x = bounce[tid * BSTRIDE + j];
            bounce[tid * BSTRIDE + j] = (x - mean) * rs * sg[j] + sbe[j];
        }
    }
    if (MODE == 1) __syncthreads();

    // ---- store: packed (MODE 0/1/2) or fp32 (MODE 3); +skip+relu for MODE 1 ----
    {
        const float* bounce = (const float*)(smem + OFF_BOUNCE);
#pragma unroll
        for (int it = 0; it < 16; ++it) {
            int idx4 = tid + it * 256;
            int row = idx4 >> 5, c4 = idx4 & 31;
            int grow = row0 + row;
            if (grow < N_NODES) {
                float4 v = *(const float4*)(bounce + row * BSTRIDE + c4 * 4);
                if (MODE == 1) {
                    if (skHi) {
                        uint2 sh = *(const uint2*)(skHi + (size_t)grow * 64 + c4 * 2);
                        uint2 sl = *(const uint2*)(skLo + (size_t)grow * 64 + c4 * 2);
                        v.x += up_lo(sh.x, sl.x); v.y += up_hi(sh.x, sl.x);
                        v.z += up_lo(sh.y, sl.y); v.w += up_hi(sh.y, sl.y);
                    }
                    v.x = fmaxf(v.x, 0.f); v.y = fmaxf(v.y, 0.f);
                    v.z = fmaxf(v.z, 0.f); v.w = fmaxf(v.w, 0.f);
                }
                if (MODE == 3) {
                    *(float4*)(outF + (size_t)grow * HID + c4 * 4) = v;
                } else {
                    float r0, r1, r2, r3;
                    unsigned h01 = pack_hi(v.x, v.y, r0, r1);
                    unsigned h23 = pack_hi(v.z, v.w, r2, r3);
                    unsigned l01 = pack_lo(r0, r1);
                    unsigned l23 = pack_lo(r2, r3);
                    *(uint2*)(outHi + (size_t)grow * 64 + c4 * 2) = make_uint2(h01, h23);
                    *(uint2*)(outLo + (size_t)grow * 64 + c4 * 2) = make_uint2(l01, l23);
                }
            }
        }
    }
}

// ---------------- launch ----------------
extern "C" void kernel_launch(void* const* d_in, const int* in_sizes, int n_in,
                              void* d_out, int out_size)
{
    const float* x       = (const float*)d_in[0];
    const int*   ei      = (const int*)  d_in[1];
    const float* emb_W   = (const float*)d_in[2];
    const float* emb_b   = (const float*)d_in[3];
    const float* lin_l_W = (const float*)d_in[4];
    const float* lin_l_b = (const float*)d_in[5];
    const float* lin_r_W = (const float*)d_in[6];
    const float* ln_g    = (const float*)d_in[7];
    const float* ln_b    = (const float*)d_in[8];
    const float* fus_W1  = (const float*)d_in[9];
    const float* fus_b1  = (const float*)d_in[10];
    const float* fus_W2  = (const float*)d_in[11];
    const float* fus_b2  = (const float*)d_in[12];
    float* out = (float*)d_out;

    unsigned *rhi, *rlo, *ahi, *alo;
    int* degi;
    cudaGetSymbolAddress((void**)&rhi, g_rhi);
    cudaGetSymbolAddress((void**)&rlo, g_rlo);
    cudaGetSymbolAddress((void**)&ahi, g_ahi);
    cudaGetSymbolAddress((void**)&alo, g_alo);
    cudaGetSymbolAddress((void**)&degi, g_degi);

    cudaFuncSetAttribute(gemm_mma<0>, cudaFuncAttributeMaxDynamicSharedMemorySize, SMEM_TOTAL);
    cudaFuncSetAttribute(gemm_mma<1>, cudaFuncAttributeMaxDynamicSharedMemorySize, SMEM_TOTAL);
    cudaFuncSetAttribute(gemm_mma<2>, cudaFuncAttributeMaxDynamicSharedMemorySize, SMEM_TOTAL);
    cudaFuncSetAttribute(gemm_mma<3>, cudaFuncAttributeMaxDynamicSharedMemorySize, SMEM_TOTAL);

    // side stream + fork/join events (host-side objects only; created once)
    static cudaStream_t s2 = nullptr;
    static cudaEvent_t evF = nullptr, evJ = nullptr;
    if (s2 == nullptr) {
        cudaStreamCreateWithFlags(&s2, cudaStreamNonBlocking);
        cudaEventCreateWithFlags(&evF, cudaEventDisableTiming);
        cudaEventCreateWithFlags(&evJ, cudaEventDisableTiming);
    }

    // fork: CSR build on s2; weight prep + embed GEMM on main
    cudaEventRecord(evF, 0);
    cudaStreamWaitEvent(s2, evF, 0);
    cudaMemsetAsync(degi, 0, N_NODES * sizeof(int), s2);
    deg_kernel<<<(N_EDGES + 255) / 256, 256, 0, s2>>>(ei);
    inv_kernel<<<(N_NODES + 255) / 256, 256, 0, s2>>>();
    scan1_kernel<<<SCAN_BLOCKS, 256, 0, s2>>>();
    scan2_kernel<<<1, 256, 0, s2>>>();
    scan3_kernel<<<SCAN_BLOCKS, 256, 0, s2>>>();
    fill_kernel<<<(N_EDGES + 255) / 256, 256, 0, s2>>>(ei);
    cudaEventRecord(evJ, s2);

    prep_w<<<(33 * 4096 + 255) / 256, 256>>>(emb_W, lin_l_W, lin_r_W, fus_W1, fus_W2);

    const int GB = (N_NODES + 127) / 128;  // 391
    const size_t RSTEP = (size_t)N_NODES * 64;

    // embedding -> reps[0] packed
    gemm_mma<0><<<GB, 256, SMEM_TOTAL>>>(x, nullptr, nullptr, nullptr, nullptr, 0, emb_b,
                                         nullptr, nullptr, nullptr, nullptr,
                                         nullptr, rhi, rlo);

    // join before aggregation needs CSR
    cudaStreamWaitEvent(0, evJ, 0);

    for (int i = 0; i < NLAYERS; i++) {
        unsigned* hhi = rhi + (size_t)i * RSTEP;
        unsigned* hlo = rlo + (size_t)i * RSTEP;
        unsigned* nhi = rhi + (size_t)(i + 1) * RSTEP;
        unsigned* nlo = rlo + (size_t)(i + 1) * RSTEP;
        agg_kernel<<<(N_NODES * 32 + 255) / 256, 256>>>(hhi, hlo);
        gemm_mma<1><<<GB, 256, SMEM_TOTAL>>>(nullptr, ahi, alo, hhi, hlo, 5 + i * 4,
                                             lin_l_b + i * HID,
                                             ln_g + i * HID, ln_b + i * HID,
                                             (i > 0) ? hhi : nullptr,
                                             (i > 0) ? hlo : nullptr,
                                             nullptr, nhi, nlo);
    }
    // fusion 1 -> g_a* packed (agg scratch reusable now)
    gemm_mma<2><<<GB, 256, SMEM_TOTAL>>>(nullptr, rhi, rlo, nullptr, nullptr, 21, fus_b1,
                                         nullptr, nullptr, nullptr, nullptr,
                                         nullptr, ahi, alo);
    // fusion 2 -> fp32 out
    gemm_mma<3><<<GB, 256, SMEM_TOTAL>>>(nullptr, ahi, alo, nullptr, nullptr, 31, fus_b2,
                                         nullptr, nullptr, nullptr, nullptr,
                                         out, nullptr, nullptr);
}